// round 11
// baseline (speedup 1.0000x reference)
#include <cuda_runtime.h>
#include <cstdint>

#define DI __device__ __forceinline__

// ---------------- problem sizes ----------------
#define B_ROWS   4096
#define IN_F     40960
#define HID      256
#define KC       64                 // fp32 K elems per chunk (2 x k32 IMMA steps)
#define NCHUNK   (IN_F / KC)        // 640
#define NBLK     128                // CTAs: 8192 rows / 64
#define TPB      256
#define WCHUNK_BYTES 32768          // W chunk: fragment-interleaved W1|W0 digit bytes

// A smem: two u8 digit planes (X1, X0), 64 rows x 64 bytes, row stride 80 (pad)
#define AROWB    80
#define APLANE   (64 * AROWB)       // 5120
#define ASTAGE   (2 * APLANE)       // 10240
#define SM_W0    0
#define SM_A0    (2 * WCHUNK_BYTES) // 65536
#define DSMEM_BYTES (2 * WCHUNK_BYTES + 2 * ASTAGE + 1024)   // ~87 KB

// ---------------- device scratch ----------------
// W digits fragment-interleaved:
// [chunk][wn_group(4)][(j*2+ks)*512 + lane*16] = {b0W1, b1W1, b0W0, b1W0}
__device__ __align__(128) uint8_t g_W[(size_t)NCHUNK * WCHUNK_BYTES];   // 20 MB
__device__ float  g_Sw[HID];        // per-column quant scale
__device__ double g_inv[HID];       // 1/(65535 * Sw[n])
__device__ float  g_x[(size_t)B_ROWS * 2 * HID];   // clipped concat [B, 512]

// ---------------- helpers ----------------
DI unsigned smem_u32(const void* p) {
    unsigned a;
    asm("{ .reg .u64 t; cvta.to.shared.u64 t, %1; cvt.u32.u64 %0, t; }" : "=r"(a) : "l"(p));
    return a;
}
DI unsigned lds32(unsigned a) {
    unsigned v;
    asm volatile("ld.shared.b32 %0, [%1];" : "=r"(v) : "r"(a));
    return v;
}
DI uint4 lds128(unsigned a) {
    uint4 v;
    asm volatile("ld.shared.v4.b32 {%0,%1,%2,%3}, [%4];"
                 : "=r"(v.x), "=r"(v.y), "=r"(v.z), "=r"(v.w) : "r"(a));
    return v;
}
DI void sts32(unsigned a, unsigned v) {
    asm volatile("st.shared.b32 [%0], %1;" :: "r"(a), "r"(v) : "memory");
}
DI void cp16(unsigned dst, const void* src) {
    asm volatile("cp.async.cg.shared.global [%0], [%1], 16;" :: "r"(dst), "l"(src) : "memory");
}
DI void cp_commit()  { asm volatile("cp.async.commit_group;" ::: "memory"); }
DI void cp_wait1()   { asm volatile("cp.async.wait_group 1;" ::: "memory"); }
DI void cp_wait0()   { asm volatile("cp.async.wait_group 0;" ::: "memory"); }

// D(s32) += A(u8, 16x32) * B(s8, 32x8)
DI void imma(int* d, unsigned a0, unsigned a1, unsigned a2, unsigned a3,
             unsigned b0, unsigned b1) {
    asm volatile(
        "mma.sync.aligned.m16n8k32.row.col.s32.u8.s8.s32 "
        "{%0,%1,%2,%3}, {%4,%5,%6,%7}, {%8,%9}, {%0,%1,%2,%3};"
        : "+r"(d[0]), "+r"(d[1]), "+r"(d[2]), "+r"(d[3])
        : "r"(a0), "r"(a1), "r"(a2), "r"(a3), "r"(b0), "r"(b1));
}

// ================= kernel 1a: per-column |W| max -> scales =================
__global__ void prep_scale_kernel(const float* __restrict__ Wft) {
    const int n   = blockIdx.x;          // 256 blocks
    const int tid = threadIdx.x;         // 256 threads
    const float* row = Wft + (size_t)n * IN_F;
    float m = 0.0f;
    for (int k = tid; k < IN_F; k += 256) m = fmaxf(m, fabsf(row[k]));
#pragma unroll
    for (int off = 16; off > 0; off >>= 1)
        m = fmaxf(m, __shfl_xor_sync(0xFFFFFFFFu, m, off));
    __shared__ float sm[8];
    if ((tid & 31) == 0) sm[tid >> 5] = m;
    __syncthreads();
    if (tid == 0) {
        float mm = sm[0];
#pragma unroll
        for (int i = 1; i < 8; i++) mm = fmaxf(mm, sm[i]);
        float Sw = 32639.0f / mm;
        g_Sw[n]  = Sw;
        g_inv[n] = 1.0 / (65535.0 * (double)Sw);
    }
}

// ================= kernel 1b: quantize W into digit fragments =================
// one thread per 16B unit: (chunk, wn_group, j, ks, lane)
__global__ void prep_w_kernel(const float* __restrict__ Wft) {
    unsigned g    = blockIdx.x * 256u + threadIdx.x;   // NCHUNK*2048 threads
    unsigned lane = g & 31u;
    unsigned ks   = (g >> 5) & 1u;
    unsigned j    = (g >> 6) & 7u;
    unsigned wg   = (g >> 9) & 3u;
    unsigned c    = g >> 11;

    unsigned n = wg * 64u + j * 8u + (lane >> 2);
    unsigned k = c * 64u + ks * 32u + (lane & 3u) * 4u;
    const float* src = Wft + (size_t)n * IN_F + k;
    float4 f0 = *(const float4*)(src);        // k .. k+3   -> b0
    float4 f1 = *(const float4*)(src + 16);   // k+16..k+19 -> b1
    float Sw = g_Sw[n];

    int W[8];
    W[0] = __float2int_rn(f0.x * Sw); W[1] = __float2int_rn(f0.y * Sw);
    W[2] = __float2int_rn(f0.z * Sw); W[3] = __float2int_rn(f0.w * Sw);
    W[4] = __float2int_rn(f1.x * Sw); W[5] = __float2int_rn(f1.y * Sw);
    W[6] = __float2int_rn(f1.z * Sw); W[7] = __float2int_rn(f1.w * Sw);

    unsigned w1b[8], w0b[8];
#pragma unroll
    for (int i = 0; i < 8; i++) {
        int hi = (W[i] + 128) >> 8;          // arithmetic shift: floor((W+128)/256)
        int lo = W[i] - (hi << 8);           // in [-128, 127]
        w1b[i] = (unsigned)hi & 255u;
        w0b[i] = (unsigned)lo & 255u;
    }
    uint4 v;
    v.x = w1b[0] | (w1b[1] << 8) | (w1b[2] << 16) | (w1b[3] << 24);   // b0 of W1
    v.y = w1b[4] | (w1b[5] << 8) | (w1b[6] << 16) | (w1b[7] << 24);   // b1 of W1
    v.z = w0b[0] | (w0b[1] << 8) | (w0b[2] << 16) | (w0b[3] << 24);   // b0 of W0
    v.w = w0b[4] | (w0b[5] << 8) | (w0b[6] << 16) | (w0b[7] << 24);   // b1 of W0
    *(uint4*)(g_W + (size_t)c * WCHUNK_BYTES + wg * 8192u + (j * 2u + ks) * 512u + lane * 16u) = v;
}

// ================= kernel 2: feature-transformer GEMM (IMMA digit scheme) ======
// C[8192,256] = A @ W^T; CTA 64 rows x 256 cols, 8 warps, warp tile 32M x 64N
__global__ void __launch_bounds__(TPB, 1)
ft_gemm_kernel(const float* __restrict__ wfeat, const float* __restrict__ bfeat) {
    extern __shared__ uint8_t dsm[];
    const int tid = threadIdx.x;
    const int w   = tid >> 5;
    const int l   = tid & 31;
    const int b   = blockIdx.x;

    const bool white = (b < NBLK / 2);
    const float* feat = white ? (wfeat + (size_t)b * 64 * IN_F)
                              : (bfeat + (size_t)(b - NBLK / 2) * 64 * IN_F);

    const int mg  = w >> 2;             // M group (0,1)
    const int wng = w & 3;              // N group (0..3)

    const unsigned sbase = (smem_u32(dsm) + 1023u) & ~1023u;
    const unsigned Wst[2] = { sbase + SM_W0, sbase + SM_W0 + WCHUNK_BYTES };
    const unsigned Ast[2] = { sbase + SM_A0, sbase + SM_A0 + ASTAGE };

    // A load mapping: thread covers rows (tid>>4)+16i, float-group (tid&15)
    const float* abase = feat + (size_t)(tid >> 4) * IN_F + (unsigned)(tid & 15) * 4u;
    const unsigned stsbase = (unsigned)(tid >> 4) * AROWB + (unsigned)(tid & 15) * 4u;

    int accT2[2][8][4], accT1[2][8][4], accT0[2][8][4];
#pragma unroll
    for (int t = 0; t < 2; t++)
#pragma unroll
        for (int j = 0; j < 8; j++)
#pragma unroll
            for (int q = 0; q < 4; q++) {
                accT2[t][j][q] = 0; accT1[t][j][q] = 0; accT0[t][j][q] = 0;
            }

    // W copy: 256 threads x 8 x 16B = 32 KB per chunk
    auto copyW = [&](int c, int st) {
        const uint8_t* src = g_W + (size_t)c * WCHUNK_BYTES + tid * 16;
        unsigned dst = Wst[st] + tid * 16;
#pragma unroll
        for (int i = 0; i < 8; i++) cp16(dst + i * 4096, src + i * 4096);
        cp_commit();
    };

    // quantize 16 floats -> u8 digit planes in stage st
    auto quantSTS = [&](const float4 av[4], int st) {
        unsigned p1 = Ast[st];            // X1 plane
        unsigned p0 = Ast[st] + APLANE;   // X0 plane
#pragma unroll
        for (int i = 0; i < 4; i++) {
            float4 f = av[i];
            unsigned X0 = __float2uint_rn(f.x * 65535.0f);
            unsigned X1 = __float2uint_rn(f.y * 65535.0f);
            unsigned X2 = __float2uint_rn(f.z * 65535.0f);
            unsigned X3 = __float2uint_rn(f.w * 65535.0f);
            unsigned hi = (X0 >> 8) | ((X1 >> 8) << 8) | ((X2 >> 8) << 16) | ((X3 >> 8) << 24);
            unsigned lo = (X0 & 255u) | ((X1 & 255u) << 8) | ((X2 & 255u) << 16) | ((X3 & 255u) << 24);
            unsigned off = stsbase + (unsigned)i * (16u * AROWB);
            sts32(p1 + off, hi);
            sts32(p0 + off, lo);
        }
    };

    // ---- prologue ----
    float4 av[4];
#pragma unroll
    for (int i = 0; i < 4; i++) av[i] = *(const float4*)(abase + (size_t)i * 16 * IN_F);
    quantSTS(av, 0);
    copyW(0, 0);
    copyW(1, 1);
    __syncthreads();

    const unsigned afrag0 = (unsigned)(mg * 32 + (l >> 2)) * AROWB + (unsigned)(l & 3) * 4u;

    for (int c = 0; c < NCHUNK; c++) {
        if (c + 1 < NCHUNK) {
#pragma unroll
            for (int i = 0; i < 4; i++)
                av[i] = *(const float4*)(abase + (size_t)i * 16 * IN_F + (size_t)(c + 1) * KC);
        }
        if (c + 1 < NCHUNK) cp_wait1(); else cp_wait0();
        __syncthreads();

        const unsigned aS = Ast[c & 1];
        const unsigned wS = Wst[c & 1] + (unsigned)wng * 8192u + (unsigned)l * 16u;

#pragma unroll
        for (int ks = 0; ks < 2; ks++) {
            unsigned aH[2][4], aL[2][4];   // X1 / X0 digit fragments per m-tile
#pragma unroll
            for (int t = 0; t < 2; t++) {
                unsigned base = aS + afrag0 + (unsigned)t * (16u * AROWB) + (unsigned)ks * 32u;
                aH[t][0] = lds32(base);
                aH[t][1] = lds32(base + 8u * AROWB);
                aH[t][2] = lds32(base + 16u);
                aH[t][3] = lds32(base + 8u * AROWB + 16u);
                aL[t][0] = lds32(base + APLANE);
                aL[t][1] = lds32(base + APLANE + 8u * AROWB);
                aL[t][2] = lds32(base + APLANE + 16u);
                aL[t][3] = lds32(base + APLANE + 8u * AROWB + 16u);
            }
#pragma unroll
            for (int j = 0; j < 8; j++) {
                uint4 bv = lds128(wS + (unsigned)(j * 2 + ks) * 512u);
#pragma unroll
                for (int t = 0; t < 2; t++) {
                    imma(accT2[t][j], aH[t][0], aH[t][1], aH[t][2], aH[t][3], bv.x, bv.y);
                    imma(accT1[t][j], aH[t][0], aH[t][1], aH[t][2], aH[t][3], bv.z, bv.w);
                    imma(accT1[t][j], aL[t][0], aL[t][1], aL[t][2], aL[t][3], bv.x, bv.y);
                    imma(accT0[t][j], aL[t][0], aL[t][1], aL[t][2], aL[t][3], bv.z, bv.w);
                }
            }
        }

        if (c + 1 < NCHUNK) quantSTS(av, (c + 1) & 1);
        __syncthreads();
        if (c + 2 < NCHUNK) copyW(c + 2, c & 1);
    }

    // ---- epilogue: reconstruct in double, clip, write concat g_x[B,512] ----
    const int rbase = (white ? b : b - NBLK / 2) * 64 + mg * 32 + (l >> 2);
    float* xbase = g_x + (white ? 0 : HID);
#pragma unroll
    for (int t = 0; t < 2; t++) {
        const int r0 = rbase + t * 16;
#pragma unroll
        for (int j = 0; j < 8; j++) {
            const int col = wng * 64 + j * 8 + (l & 3) * 2;
            double inv0 = g_inv[col], inv1 = g_inv[col + 1];
            double d0 = (65536.0 * (double)accT2[t][j][0] + 256.0 * (double)accT1[t][j][0]
                         + (double)accT0[t][j][0]) * inv0;
            double d1 = (65536.0 * (double)accT2[t][j][1] + 256.0 * (double)accT1[t][j][1]
                         + (double)accT0[t][j][1]) * inv1;
            double d2 = (65536.0 * (double)accT2[t][j][2] + 256.0 * (double)accT1[t][j][2]
                         + (double)accT0[t][j][2]) * inv0;
            double d3 = (65536.0 * (double)accT2[t][j][3] + 256.0 * (double)accT1[t][j][3]
                         + (double)accT0[t][j][3]) * inv1;
            float2 v0, v1;
            v0.x = fminf(fmaxf((float)d0, 0.0f), 1.0f);
            v0.y = fminf(fmaxf((float)d1, 0.0f), 1.0f);
            v1.x = fminf(fmaxf((float)d2, 0.0f), 1.0f);
            v1.y = fminf(fmaxf((float)d3, 0.0f), 1.0f);
            *(float2*)(xbase + (size_t)r0 * 512 + col)       = v0;
            *(float2*)(xbase + (size_t)(r0 + 8) * 512 + col) = v1;
        }
    }
}

// ================= kernel 3: MLP 512 -> 32 -> 32 -> 1 (warp per row) =================
__global__ void mlp_kernel(const float* __restrict__ W1, const float* __restrict__ b1,
                           const float* __restrict__ W2, const float* __restrict__ b2,
                           const float* __restrict__ W3, const float* __restrict__ b3,
                           const float* __restrict__ stm, float* __restrict__ out) {
    const int warp = (blockIdx.x * blockDim.x + threadIdx.x) >> 5;
    const int lid  = threadIdx.x & 31;
    if (warp >= B_ROWS) return;
    const float* xr = g_x + (size_t)warp * 512;

    float xv[16];
#pragma unroll
    for (int i = 0; i < 16; i++) xv[i] = xr[lid + 32 * i];

    float h1 = 0.0f;
#pragma unroll
    for (int j = 0; j < 32; j++) {
        const float* wrow = W1 + j * 512;
        float a = 0.0f;
#pragma unroll
        for (int i = 0; i < 16; i++) a += xv[i] * wrow[lid + 32 * i];
#pragma unroll
        for (int off = 16; off > 0; off >>= 1) a += __shfl_xor_sync(0xFFFFFFFFu, a, off);
        a = fmaxf(a + b1[j], 0.0f);
        if (lid == j) h1 = a;
    }

    float a2 = b2[lid];
#pragma unroll
    for (int k = 0; k < 32; k++)
        a2 += __shfl_sync(0xFFFFFFFFu, h1, k) * W2[lid * 32 + k];
    float h2 = fmaxf(a2, 0.0f);

    float v = h2 * W3[lid];
#pragma unroll
    for (int off = 16; off > 0; off >>= 1) v += __shfl_xor_sync(0xFFFFFFFFu, v, off);

    if (lid == 0) out[warp] = (v + b3[0]) * stm[warp];
}

// ================= host launcher =================
extern "C" void kernel_launch(void* const* d_in, const int* in_sizes, int n_in,
                              void* d_out, int out_size) {
    const float* wfeat = (const float*)d_in[0];
    const float* bfeat = (const float*)d_in[1];
    const float* stm   = (const float*)d_in[2];
    const float* Wft   = (const float*)d_in[3];
    const float* W1    = (const float*)d_in[4];
    const float* b1    = (const float*)d_in[5];
    const float* W2    = (const float*)d_in[6];
    const float* b2    = (const float*)d_in[7];
    const float* W3    = (const float*)d_in[8];
    const float* b3    = (const float*)d_in[9];

    static bool attr_set = false;
    if (!attr_set) {
        cudaFuncSetAttribute(ft_gemm_kernel,
                             cudaFuncAttributeMaxDynamicSharedMemorySize, DSMEM_BYTES);
        attr_set = true;
    }

    prep_scale_kernel<<<HID, 256>>>(Wft);
    prep_w_kernel<<<(NCHUNK * 2048) / 256, 256>>>(Wft);
    ft_gemm_kernel<<<NBLK, TPB, DSMEM_BYTES>>>(wfeat, bfeat);
    mlp_kernel<<<(B_ROWS * 32) / 256, 256>>>(W1, b1, W2, b2, W3, b3, stm, (float*)d_out);
}